// round 17
// baseline (speedup 1.0000x reference)
#include <cuda_runtime.h>
#include <math.h>

#define NEARV     2.0f
#define FARV      6.0f
#define FAR_DIST  1e10f
#define S         128
#define TPB       128          // 4 warps per block
#define NBLK      1184         // 148 SMs x 8 blocks: persistent grid
#define MAX_BLK   16384
#define FULL      0xffffffffu
#define ONE_EPS   1.0000000001f   // 1 + 1e-10

// Deterministic scratch for the fused scalar reduction (no allocations allowed).
__device__ float        g_partials[MAX_BLK];
__device__ unsigned int g_count = 0;

__global__ __launch_bounds__(TPB, 6) void integrate_kernel(
    const float* __restrict__ raw,     // [N, S, 4]
    const float* __restrict__ zvals,   // [N, S]
    const float* __restrict__ rays_d,  // [N, 3]
    float* __restrict__ out,           // [3N chs | N depth | 1 scalar]
    int N)
{
    __shared__ float  sh_ent[TPB / 32];
    __shared__ double sh_red[TPB];
    __shared__ bool   sh_last;

    const int warp  = threadIdx.x >> 5;
    const int lane  = threadIdx.x & 31;
    const int gwarp = blockIdx.x * (TPB >> 5) + warp;
    const int TOTW  = NBLK * (TPB >> 5);           // 4736 warps total

    const float4* rp4 = (const float4*)raw;

    float ent_acc = 0.0f;

    // ---- loader: 9 independent coalesced LDGs (8x512B f4 + 4x128B z + rd) ----
    auto loadbuf = [&](int ry, float4 (&r)[4], float (&z)[4], float3& rd) {
        const float4* rp = rp4 + (size_t)ry * S;
        const float*  zp = zvals + (size_t)ry * S;
        #pragma unroll
        for (int k = 0; k < 4; k++) r[k] = rp[32 * k + lane];
        #pragma unroll
        for (int k = 0; k < 4; k++) z[k] = zp[32 * k + lane];
        const float* rdp = rays_d + (size_t)ry * 3;
        rd.x = rdp[0]; rd.y = rdp[1]; rd.z = rdp[2];
    };

    // ---- full per-ray pipeline body (width-32 scan; lane owns j = 32k+lane) --
    auto compute = [&](const float4 (&r)[4], const float (&z)[4],
                       const float3 rd, int ry) {
        const float nrm = sqrtf(rd.x * rd.x + rd.y * rd.y + rd.z * rd.z);

        float t[4];
        #pragma unroll
        for (int k = 0; k < 4; k++) {
            const float znext = __shfl_down_sync(FULL, z[k], 1);
            float dist;
            if (k < 3) {
                const float zhead = __shfl_sync(FULL, z[k + 1], 0);
                dist = (lane == 31) ? (zhead - z[k]) : (znext - z[k]);
            } else {
                dist = (lane == 31) ? FAR_DIST : (znext - z[k]);
            }
            dist *= nrm;
            t[k] = __expf(-fmaxf(r[k].w, 0.0f) * dist) + 1e-10f;
        }

        // 4 width-32 inclusive multiplicative scans
        #pragma unroll
        for (int off = 1; off < 32; off <<= 1) {
            #pragma unroll
            for (int k = 0; k < 4; k++) {
                const float v = __shfl_up_sync(FULL, t[k], off);
                if (lane >= off) t[k] *= v;
            }
        }

        // weights & accumulation: w = Ck*(ONE_EPS*excl - incl)
        float c0 = 0.f, c1 = 0.f, c2 = 0.f, wz = 0.f, ws = 0.f, S1 = 0.f;
        float Ck = 1.0f;
        #pragma unroll
        for (int k = 0; k < 4; k++) {
            const float e  = __shfl_up_sync(FULL, t[k], 1);
            const float ex = (lane == 0) ? 1.0f : e;
            const float P  = __shfl_sync(FULL, t[k], 31);
            const float w  = Ck * (ONE_EPS * ex - t[k]);
            c0 += w * r[k].x;
            c1 += w * r[k].y;
            c2 += w * r[k].z;
            wz += w * z[k];
            ws += w;
            S1 += w * __logf(fmaxf(w, 1e-35f));
            Ck *= P;
        }

        // packed reduction: xor16 on 6 values, then 3 packed values x 4 rounds
        c0 += __shfl_xor_sync(FULL, c0, 16);
        c1 += __shfl_xor_sync(FULL, c1, 16);
        c2 += __shfl_xor_sync(FULL, c2, 16);
        wz += __shfl_xor_sync(FULL, wz, 16);
        ws += __shfl_xor_sync(FULL, ws, 16);
        S1 += __shfl_xor_sync(FULL, S1, 16);
        float A = (lane < 16) ? c0 : wz;
        float B = (lane < 16) ? c1 : ws;
        float C = (lane < 16) ? c2 : S1;
        #pragma unroll
        for (int off = 8; off > 0; off >>= 1) {
            A += __shfl_xor_sync(FULL, A, off);
            B += __shfl_xor_sync(FULL, B, off);
            C += __shfl_xor_sync(FULL, C, off);
        }
        // lanes 0..15: Σc0 Σc1 Σc2 ; lanes 16..31: Σwz Σws ΣS1

        if (lane == 0) {
            out[(size_t)ry * 3 + 0] = A;
            out[(size_t)ry * 3 + 1] = B;
            out[(size_t)ry * 3 + 2] = C;
        }
        if (lane == 16) {
            const float wzs = A, wss = B, s1s = C;
            out[(size_t)3 * N + ry] = (1.5f * wss - 0.25f * wzs) / (wss + 1e-5f);
            const float invD = 1.0f / (1.0f + 1e-6f);
            float e2 = invD * (s1s + (-9.999995e-7f) * wss);
            const float p_last = (1.0f - wss + 1e-6f) * invD;
            if (p_last > 0.0f) e2 += p_last * __logf(p_last);
            ent_acc += e2;                       // lane 16 accumulates
        }
    };

    // ---- software-pipelined persistent loop: 2x unrolled ping-pong ----
    if (gwarp < N) {
        float4 rA[4], rB[4];
        float  zA[4], zB[4];
        float3 dA, dB;
        int ray = gwarp;
        loadbuf(ray, rA, zA, dA);
        for (;;) {
            int nray = ray + TOTW;
            bool hn = (nray < N);
            if (hn) loadbuf(nray, rB, zB, dB);   // in flight during compute(A)
            compute(rA, zA, dA, ray);
            if (!hn) break;
            ray = nray;

            nray = ray + TOTW;
            hn = (nray < N);
            if (hn) loadbuf(nray, rA, zA, dA);   // in flight during compute(B)
            compute(rB, zB, dB, ray);
            if (!hn) break;
            ray = nray;
        }
    }

    if (lane == 16) sh_ent[warp] = ent_acc;
    __syncthreads();

    // ---- fused deterministic grid reduction (threadfence-reduction pattern) ----
    if (threadIdx.x == 0) {
        float s = 0.0f;
        #pragma unroll
        for (int w = 0; w < TPB / 32; w++) s += sh_ent[w];
        g_partials[blockIdx.x] = s;
        __threadfence();
        const unsigned int done = atomicAdd(&g_count, 1u);
        sh_last = (done == gridDim.x - 1);
    }
    __syncthreads();

    if (sh_last) {
        double s = 0.0;
        for (int i = threadIdx.x; i < (int)gridDim.x; i += TPB)
            s += (double)g_partials[i];
        sh_red[threadIdx.x] = s;
        __syncthreads();
        #pragma unroll
        for (int off = TPB / 2; off > 0; off >>= 1) {
            if (threadIdx.x < off) sh_red[threadIdx.x] += sh_red[threadIdx.x + off];
            __syncthreads();
        }
        if (threadIdx.x == 0) {
            out[(size_t)4 * N] = (float)(-sh_red[0]);   // sparsity_loss
            g_count = 0;                                 // re-arm for next replay
        }
    }
}

extern "C" void kernel_launch(void* const* d_in, const int* in_sizes, int n_in,
                              void* d_out, int out_size)
{
    const float* raw    = (const float*)d_in[0];
    const float* zvals  = (const float*)d_in[1];
    const float* rays_d = (const float*)d_in[2];
    float* out = (float*)d_out;

    const int N = in_sizes[2] / 3;               // rays_d is [N,3]
    integrate_kernel<<<NBLK, TPB>>>(raw, zvals, rays_d, out, N);
}